// round 6
// baseline (speedup 1.0000x reference)
#include <cuda_runtime.h>
#include <cuda_bf16.h>
#include <math.h>
#include <stdint.h>

typedef unsigned long long ull;

#define NB 16
#define NH 64
#define NL 16384
#define NN 64
#define NCD 32
#define CT 64                 // chunk length
#define NCK (NL / CT)         // 256 chunks per (b,h)
#define KDIM 192              // [u(64) | sr(64) | si(64)]

// ---------------- device scratch (statics per harness rules) ----------------
__device__ __nv_bfloat16 g_uhi[(size_t)NB * NH * NL];
__device__ __nv_bfloat16 g_ulo[(size_t)NB * NH * NL];
__device__ float         g_e  [(size_t)NB * NH * NCK * 128];   // chunk-end sums
__device__ __nv_bfloat16 g_shi[(size_t)NB * NH * NCK * 128];   // entry states hi
__device__ __nv_bfloat16 g_slo[(size_t)NB * NH * NCK * 128];   // entry states lo
__device__ __nv_bfloat16 g_Ghi[(size_t)NH * CT * KDIM];        // main B [64 x 192]/head
__device__ __nv_bfloat16 g_Glo[(size_t)NH * CT * KDIM];
__device__ __nv_bfloat16 g_Ehi[(size_t)NH * 128 * CT];         // E B [128 x 64]/head
__device__ __nv_bfloat16 g_Elo[(size_t)NH * 128 * CT];
__device__ float         g_w64r[NH * NN], g_w64i[NH * NN];
__device__ float         g_film[2 * NB * NH];

// ---------------- helpers ----------------
__device__ __forceinline__ ull fma2(ull a, ull b, ull c) {
    ull d; asm("fma.rn.f32x2 %0, %1, %2, %3;" : "=l"(d) : "l"(a), "l"(b), "l"(c)); return d;
}
union F2U { float2 f; ull u; };
__device__ __forceinline__ float2 unpack2(ull v) { F2U t; t.u = v; return t.f; }

__device__ __forceinline__ float gelu_exact(float v) {
    return 0.5f * v * (1.0f + erff(v * 0.7071067811865475f));
}
__device__ __forceinline__ void bsplit(float v, __nv_bfloat16& hi, __nv_bfloat16& lo) {
    hi = __float2bfloat16(v);
    lo = __float2bfloat16(v - __bfloat162float(hi));
}

// warp-level bf16 MMA m16n8k16, fp32 accumulate in place
__device__ __forceinline__ void mma16816(float* d, const uint32_t* a,
                                         uint32_t b0, uint32_t b1) {
    asm volatile(
        "mma.sync.aligned.m16n8k16.row.col.f32.bf16.bf16.f32 "
        "{%0,%1,%2,%3}, {%4,%5,%6,%7}, {%8,%9}, {%0,%1,%2,%3};"
        : "+f"(d[0]), "+f"(d[1]), "+f"(d[2]), "+f"(d[3])
        : "r"(a[0]), "r"(a[1]), "r"(a[2]), "r"(a[3]), "r"(b0), "r"(b1));
}

// A fragment (m16k16, row-major) from global bf16: row/ld/col in elements
__device__ __forceinline__ void load_afrag(uint32_t* a, const __nv_bfloat16* base,
                                           int row, int ld, int col) {
    a[0] = *(const uint32_t*)(base + (size_t)row * ld + col);
    a[1] = *(const uint32_t*)(base + (size_t)(row + 8) * ld + col);
    a[2] = *(const uint32_t*)(base + (size_t)row * ld + col + 8);
    a[3] = *(const uint32_t*)(base + (size_t)(row + 8) * ld + col + 8);
}

// w = exp(dt*A), c = 2*C*(w-1)/A for this lane's two states
__device__ __forceinline__ void lane_wc(int h, int lane,
                                        const float* __restrict__ log_dt,
                                        const float* __restrict__ log_A_real,
                                        const float* __restrict__ A_imag,
                                        const float* __restrict__ C_re,
                                        const float* __restrict__ C_im,
                                        float wr[2], float wi[2],
                                        float cr[2], float ci[2])
{
    const float dt = expf(log_dt[h]);
    #pragma unroll
    for (int s = 0; s < 2; s++) {
        int n = 2 * lane + s;
        float Ar = -expf(log_A_real[h * NN + n]);
        float Ai = A_imag[h * NN + n];
        float er = expf(Ar * dt);
        float sn, cs;
        sincosf(Ai * dt, &sn, &cs);
        wr[s] = er * cs; wi[s] = er * sn;
        float Er = wr[s] - 1.0f, Ei = wi[s];
        float inv = 1.0f / (Ar * Ar + Ai * Ai);
        float Fr = (Er * Ar + Ei * Ai) * inv;
        float Fi = (Ei * Ar - Er * Ai) * inv;
        float Cr = C_re[h * NN + n], Ci = C_im[h * NN + n];
        cr[s] = 2.0f * (Cr * Fr - Ci * Fi);
        ci[s] = 2.0f * (Cr * Fi + Ci * Fr);
    }
}

// =====================================================================
// Kernel 1: premix  u = gelu(W x + b) -> bf16 hi/lo
// =====================================================================
__global__ __launch_bounds__(256, 2) void premix_kernel(
    const float* __restrict__ x, const float* __restrict__ W,
    const float* __restrict__ b_lin)
{
    extern __shared__ float2 sm2[];
    float2* xs = sm2;
    float2* wd = sm2 + NH * 128;

    const int tid = threadIdx.x;
    const int b   = blockIdx.y;
    const int l0  = blockIdx.x * 256;

    for (int i = tid; i < NH * NH; i += 256) {
        float wv = W[i];
        wd[i] = make_float2(wv, wv);
    }
    const float* xb = x + ((size_t)b * NH) * NL + l0;
    for (int i = tid; i < NH * 128; i += 256) {
        int h = i >> 7, p = i & 127;
        xs[i] = *(const float2*)(xb + (size_t)h * NL + 2 * p);
    }
    __syncthreads();

    const int tg   = tid >> 5;
    const int lane = tid & 31;

    ull acc[8][4];
    #pragma unroll
    for (int j = 0; j < 8; j++)
        #pragma unroll
        for (int p = 0; p < 4; p++) acc[j][p] = 0ULL;

    #pragma unroll 4
    for (int h = 0; h < NH; h++) {
        ull xp[4];
        #pragma unroll
        for (int p = 0; p < 4; p++)
            xp[p] = *(const ull*)&xs[h * 128 + lane + 32 * p];
        #pragma unroll
        for (int j = 0; j < 8; j++) {
            ull wv = *(const ull*)&wd[(tg * 8 + j) * NH + h];
            #pragma unroll
            for (int p = 0; p < 4; p++) acc[j][p] = fma2(wv, xp[p], acc[j][p]);
        }
    }

    #pragma unroll
    for (int j = 0; j < 8; j++) {
        int g = tg * 8 + j;
        float bl = b_lin[g];
        size_t base = ((size_t)b * NH + g) * NL + l0;
        __nv_bfloat162* uh = (__nv_bfloat162*)(g_uhi + base);
        __nv_bfloat162* ul = (__nv_bfloat162*)(g_ulo + base);
        #pragma unroll
        for (int p = 0; p < 4; p++) {
            float2 v = unpack2(acc[j][p]);
            float a0 = gelu_exact(v.x + bl), a1 = gelu_exact(v.y + bl);
            __nv_bfloat162 hh, ll;
            bsplit(a0, hh.x, ll.x);
            bsplit(a1, hh.y, ll.y);
            uh[lane + 32 * p] = hh;
            ul[lane + 32 * p] = ll;
        }
    }
}

// =====================================================================
// Kernel 2: per-head constants (G, E, w^64, FiLM). One warp per head.
// =====================================================================
__global__ __launch_bounds__(128) void consts_kernel(
    const float* __restrict__ log_dt, const float* __restrict__ log_A_real,
    const float* __restrict__ A_imag, const float* __restrict__ C_re,
    const float* __restrict__ C_im,   const float* __restrict__ Dvec,
    const float* __restrict__ cond,   const float* __restrict__ film_W,
    const float* __restrict__ film_b)
{
    __shared__ float Ks[4][CT];
    const int w    = threadIdx.x >> 5;
    const int lane = threadIdx.x & 31;
    const int h    = blockIdx.x * 4 + w;
    const int n0   = 2 * lane, n1 = 2 * lane + 1;

    float wr[2], wi[2], cr[2], ci[2];
    lane_wc(h, lane, log_dt, log_A_real, A_imag, C_re, C_im, wr, wi, cr, ci);

    // K taps: K[m] = sum_n Re(c_n w_n^m)
    {
        float pr[2] = {cr[0], cr[1]}, pi[2] = {ci[0], ci[1]};
        for (int m = 0; m < CT; m++) {
            float v = pr[0] + pr[1];
            #pragma unroll
            for (int o = 16; o > 0; o >>= 1) v += __shfl_xor_sync(0xffffffffu, v, o);
            if (lane == 0) Ks[w][m] = v;
            #pragma unroll
            for (int s = 0; s < 2; s++) {
                float nr = pr[s] * wr[s] - pi[s] * wi[s];
                pi[s] = pr[s] * wi[s] + pi[s] * wr[s];
                pr[s] = nr;
            }
        }
    }
    __syncwarp();
    const float Dh = Dvec[h];

    // G Toeplitz block (cols 0..63), D folded into diagonal
    for (int t = 0; t < CT; t++) {
        size_t row = (size_t)h * CT * KDIM + (size_t)t * KDIM;
        #pragma unroll
        for (int kk = 0; kk < 2; kk++) {
            int k = lane + 32 * kk;
            float val = (k <= t) ? (Ks[w][t - k] + (k == t ? Dh : 0.0f)) : 0.0f;
            bsplit(val, g_Ghi[row + k], g_Glo[row + k]);
        }
    }

    // correction cols: p = c*w^{t+1}
    {
        float pr[2], pi[2];
        #pragma unroll
        for (int s = 0; s < 2; s++) {
            pr[s] = cr[s] * wr[s] - ci[s] * wi[s];
            pi[s] = cr[s] * wi[s] + ci[s] * wr[s];
        }
        for (int t = 0; t < CT; t++) {
            size_t row = (size_t)h * CT * KDIM + (size_t)t * KDIM;
            bsplit( pr[0], g_Ghi[row +  64 + n0], g_Glo[row +  64 + n0]);
            bsplit( pr[1], g_Ghi[row +  64 + n1], g_Glo[row +  64 + n1]);
            bsplit(-pi[0], g_Ghi[row + 128 + n0], g_Glo[row + 128 + n0]);
            bsplit(-pi[1], g_Ghi[row + 128 + n1], g_Glo[row + 128 + n1]);
            #pragma unroll
            for (int s = 0; s < 2; s++) {
                float nr = pr[s] * wr[s] - pi[s] * wi[s];
                pi[s] = pr[s] * wi[s] + pi[s] * wr[s];
                pr[s] = nr;
            }
        }
    }

    // E matrix: rows n (Re) and 64+n (Im); E[n][k] = w^{63-k}
    {
        float qr[2] = {1.0f, 1.0f}, qi[2] = {0.0f, 0.0f};
        for (int k = CT - 1; k >= 0; k--) {
            size_t base = (size_t)h * 128 * CT;
            bsplit(qr[0], g_Ehi[base + (size_t)n0 * CT + k],        g_Elo[base + (size_t)n0 * CT + k]);
            bsplit(qr[1], g_Ehi[base + (size_t)n1 * CT + k],        g_Elo[base + (size_t)n1 * CT + k]);
            bsplit(qi[0], g_Ehi[base + (size_t)(64 + n0) * CT + k], g_Elo[base + (size_t)(64 + n0) * CT + k]);
            bsplit(qi[1], g_Ehi[base + (size_t)(64 + n1) * CT + k], g_Elo[base + (size_t)(64 + n1) * CT + k]);
            #pragma unroll
            for (int s = 0; s < 2; s++) {
                float nr = qr[s] * wr[s] - qi[s] * wi[s];
                qi[s] = qr[s] * wi[s] + qi[s] * wr[s];
                qr[s] = nr;
            }
        }
    }

    // w^64 via 6 squarings
    {
        float tr[2] = {wr[0], wr[1]}, ti[2] = {wi[0], wi[1]};
        for (int k = 0; k < 6; k++) {
            #pragma unroll
            for (int s = 0; s < 2; s++) {
                float nr = tr[s] * tr[s] - ti[s] * ti[s];
                ti[s] = 2.0f * tr[s] * ti[s];
                tr[s] = nr;
            }
        }
        g_w64r[h * NN + n0] = tr[0]; g_w64r[h * NN + n1] = tr[1];
        g_w64i[h * NN + n0] = ti[0]; g_w64i[h * NN + n1] = ti[1];
    }

    // FiLM per (b,h)
    for (int b = 0; b < NB; b++) {
        float cv = cond[b * NCD + lane];
        float gv = cv * film_W[h * NCD + lane];
        float bv = cv * film_W[(NH + h) * NCD + lane];
        #pragma unroll
        for (int o = 16; o > 0; o >>= 1) {
            gv += __shfl_xor_sync(0xffffffffu, gv, o);
            bv += __shfl_xor_sync(0xffffffffu, bv, o);
        }
        if (lane == 0) {
            g_film[b * NH + h]           = gv + film_b[h];
            g_film[NB * NH + b * NH + h] = bv + film_b[NH + h];
        }
    }
}

// =====================================================================
// Kernel 3: E-GEMM  e[chunk][0..127] = E_h[128x64] . u_chunk  (warp MMA)
// grid: 1024 CTAs (one per (b,h)), 512 threads (16 warps x 16 chunks).
// =====================================================================
__global__ __launch_bounds__(512, 1) void egemm_kernel()
{
    __shared__ __nv_bfloat16 Eh[128 * 72];
    __shared__ __nv_bfloat16 El[128 * 72];

    const int tid  = threadIdx.x;
    const int warp = tid >> 5;
    const int lane = tid & 31;
    const int g    = lane >> 2;
    const int cq   = lane & 3;

    const int bh = blockIdx.x;
    const int h  = bh & 63;

    // stage E (hi/lo) with pad-72 rows (conflict-free fragment LDS)
    const uint4* srcH = (const uint4*)(g_Ehi + (size_t)h * 128 * CT);
    const uint4* srcL = (const uint4*)(g_Elo + (size_t)h * 128 * CT);
    for (int i = tid; i < 1024; i += 512) {
        int row = i >> 3, v = i & 7;
        *(uint4*)&Eh[row * 72 + v * 8] = srcH[i];
        *(uint4*)&El[row * 72 + v * 8] = srcL[i];
    }
    __syncthreads();

    float acc[16][4];
    #pragma unroll
    for (int nt = 0; nt < 16; nt++)
        #pragma unroll
        for (int q = 0; q < 4; q++) acc[nt][q] = 0.0f;

    const int m0 = warp * 16;
    const __nv_bfloat16* uH = g_uhi + (size_t)bh * NL;
    const __nv_bfloat16* uL = g_ulo + (size_t)bh * NL;
    const __nv_bfloat16* Ap[3] = {uH, uH, uL};
    const __nv_bfloat16* Bp[3] = {Eh, El, Eh};

    #pragma unroll
    for (int sp = 0; sp < 3; sp++) {
        #pragma unroll
        for (int kt = 0; kt < 4; kt++) {
            uint32_t a[4];
            load_afrag(a, Ap[sp], m0 + g, CT, kt * 16 + 2 * cq);
            #pragma unroll
            for (int nt = 0; nt < 16; nt++) {
                const __nv_bfloat16* Brow = Bp[sp] + (nt * 8 + g) * 72 + kt * 16 + 2 * cq;
                uint32_t b0 = *(const uint32_t*)Brow;
                uint32_t b1 = *(const uint32_t*)(Brow + 8);
                mma16816(acc[nt], a, b0, b1);
            }
        }
    }

    float* eb = g_e + ((size_t)bh * NCK) * 128;
    #pragma unroll
    for (int nt = 0; nt < 16; nt++) {
        int col = nt * 8 + 2 * cq;
        *(float2*)&eb[(size_t)(m0 + g) * 128 + col]     = make_float2(acc[nt][0], acc[nt][1]);
        *(float2*)&eb[(size_t)(m0 + g + 8) * 128 + col] = make_float2(acc[nt][2], acc[nt][3]);
    }
}

// =====================================================================
// Kernel 4: inter-chunk scan of entry states; writes s hi/lo bf16.
// One warp per (b,h).  s_{c+1} = w^64 * s_c + e_c, s_0 = 0.
// =====================================================================
__global__ __launch_bounds__(128) void chunk_scan_kernel()
{
    const int w    = threadIdx.x >> 5;
    const int lane = threadIdx.x & 31;
    const int bh   = blockIdx.x * 4 + w;
    const int h    = bh & 63;
    const int n0   = 2 * lane, n1 = n0 + 1;

    const float w64r0 = g_w64r[h * NN + n0], w64i0 = g_w64i[h * NN + n0];
    const float w64r1 = g_w64r[h * NN + n1], w64i1 = g_w64i[h * NN + n1];

    float sr0 = 0.f, si0 = 0.f, sr1 = 0.f, si1 = 0.f;

    const float2* ep = (const float2*)g_e;
    float2 erb[4], eib[4];
    #pragma unroll
    for (int j = 0; j < 4; j++) {
        size_t o = ((size_t)bh * NCK + j) * 64;
        erb[j] = ep[o + lane];
        eib[j] = ep[o + 32 + lane];
    }

    #pragma unroll 4
    for (int c = 0; c < NCK; c++) {
        const int sl = c & 3;

        size_t sb = ((size_t)bh * NCK + c) * 128;
        __nv_bfloat162 hre, lre, him, lim;
        bsplit(sr0, hre.x, lre.x); bsplit(sr1, hre.y, lre.y);
        bsplit(si0, him.x, lim.x); bsplit(si1, him.y, lim.y);
        ((__nv_bfloat162*)(g_shi + sb))[lane]      = hre;
        ((__nv_bfloat162*)(g_shi + sb))[32 + lane] = him;
        ((__nv_bfloat162*)(g_slo + sb))[lane]      = lre;
        ((__nv_bfloat162*)(g_slo + sb))[32 + lane] = lim;

        float2 er = erb[sl], ei = eib[sl];
        if (c + 4 < NCK) {
            size_t o = ((size_t)bh * NCK + c + 4) * 64;
            erb[sl] = ep[o + lane];
            eib[sl] = ep[o + 32 + lane];
        }

        float nr0 = w64r0 * sr0 - w64i0 * si0 + er.x;
        float ni0 = w64r0 * si0 + w64i0 * sr0 + ei.x;
        float nr1 = w64r1 * sr1 - w64i1 * si1 + er.y;
        float ni1 = w64r1 * si1 + w64i1 * sr1 + ei.y;
        sr0 = nr0; si0 = ni0; sr1 = nr1; si1 = ni1;
    }
}

// =====================================================================
// Kernel 5: main GEMM  y[chunk][t] = G_h[64x192] . [u|sr|si]  (warp MMA)
// + fused FiLM + GELU + residual epilogue.
// grid: 1024 CTAs (one per (b,h)), 256 threads (8 warps x 32 chunks).
// =====================================================================
__global__ __launch_bounds__(256, 2) void maingemm_kernel(
    const float* __restrict__ x, const float* __restrict__ res_w,
    float* __restrict__ out)
{
    extern __shared__ __nv_bfloat16 gsm[];
    __nv_bfloat16* Gh = gsm;
    __nv_bfloat16* Gl = gsm + 64 * 200;

    const int tid  = threadIdx.x;
    const int warp = tid >> 5;
    const int lane = tid & 31;
    const int g    = lane >> 2;
    const int cq   = lane & 3;

    const int bh = blockIdx.x;
    const int h  = bh & 63;

    // stage G (hi/lo) with pad-200 rows
    const uint4* srcH = (const uint4*)(g_Ghi + (size_t)h * CT * KDIM);
    const uint4* srcL = (const uint4*)(g_Glo + (size_t)h * CT * KDIM);
    for (int i = tid; i < 1536; i += 256) {
        int row = i / 24, v = i - row * 24;
        *(uint4*)&Gh[row * 200 + v * 8] = srcH[i];
        *(uint4*)&Gl[row * 200 + v * 8] = srcL[i];
    }
    __syncthreads();

    float acc[2][8][4];
    #pragma unroll
    for (int mt = 0; mt < 2; mt++)
        #pragma unroll
        for (int nt = 0; nt < 8; nt++)
            #pragma unroll
            for (int q = 0; q < 4; q++) acc[mt][nt][q] = 0.0f;

    const int mw = warp * 32;
    const __nv_bfloat16* uH = g_uhi + (size_t)bh * NL;
    const __nv_bfloat16* uL = g_ulo + (size_t)bh * NL;
    const __nv_bfloat16* sH = g_shi + (size_t)bh * NCK * 128;
    const __nv_bfloat16* sL = g_slo + (size_t)bh * NCK * 128;
    const __nv_bfloat16* Au[3] = {uH, uH, uL};
    const __nv_bfloat16* As[3] = {sH, sH, sL};
    const __nv_bfloat16* Bp[3] = {Gh, Gl, Gh};

    #pragma unroll
    for (int sp = 0; sp < 3; sp++) {
        #pragma unroll
        for (int kt = 0; kt < 12; kt++) {
            uint32_t a[2][4];
            if (kt < 4) {
                int col = kt * 16 + 2 * cq;
                load_afrag(a[0], Au[sp], mw + g,      CT, col);
                load_afrag(a[1], Au[sp], mw + 16 + g, CT, col);
            } else {
                int col = kt * 16 - 64 + 2 * cq;
                load_afrag(a[0], As[sp], mw + g,      128, col);
                load_afrag(a[1], As[sp], mw + 16 + g, 128, col);
            }
            #pragma unroll
            for (int nt = 0; nt < 8; nt++) {
                const __nv_bfloat16* Brow = Bp[sp] + (nt * 8 + g) * 200 + kt * 16 + 2 * cq;
                uint32_t b0 = *(const uint32_t*)Brow;
                uint32_t b1 = *(const uint32_t*)(Brow + 8);
                mma16816(acc[0][nt], a[0], b0, b1);
                mma16816(acc[1][nt], a[1], b0, b1);
            }
        }
    }

    // ---- epilogue: FiLM + gelu + residual ----
    const float gv  = g_film[bh];
    const float bv  = g_film[NB * NH + bh];
    const float rwv = res_w[h];
    const size_t lb = (size_t)bh * NL;

    #pragma unroll
    for (int mt = 0; mt < 2; mt++) {
        #pragma unroll
        for (int nt = 0; nt < 8; nt++) {
            int mrow = mw + mt * 16 + g;
            int col  = nt * 8 + 2 * cq;
            size_t l0 = lb + (size_t)mrow * CT + col;
            size_t l1 = lb + (size_t)(mrow + 8) * CT + col;
            float2 x0 = *(const float2*)(x + l0);
            float2 x1 = *(const float2*)(x + l1);
            float2 o0, o1;
            o0.x = gelu_exact(acc[mt][nt][0] * gv + bv) + x0.x * rwv;
            o0.y = gelu_exact(acc[mt][nt][1] * gv + bv) + x0.y * rwv;
            o1.x = gelu_exact(acc[mt][nt][2] * gv + bv) + x1.x * rwv;
            o1.y = gelu_exact(acc[mt][nt][3] * gv + bv) + x1.y * rwv;
            *(float2*)(out + l0) = o0;
            *(float2*)(out + l1) = o1;
        }
    }
}

// =====================================================================
extern "C" void kernel_launch(void* const* d_in, const int* in_sizes, int n_in,
                              void* d_out, int out_size)
{
    (void)in_sizes; (void)n_in; (void)out_size;
    const float* x      = (const float*)d_in[0];
    const float* cond   = (const float*)d_in[1];
    const float* W      = (const float*)d_in[2];
    const float* b_lin  = (const float*)d_in[3];
    const float* log_dt = (const float*)d_in[4];
    const float* lAr    = (const float*)d_in[5];
    const float* Aim    = (const float*)d_in[6];
    const float* Cre    = (const float*)d_in[7];
    const float* Cim    = (const float*)d_in[8];
    const float* Dv     = (const float*)d_in[9];
    const float* fW     = (const float*)d_in[10];
    const float* fb     = (const float*)d_in[11];
    const float* rw     = (const float*)d_in[12];
    float* out = (float*)d_out;

    cudaFuncSetAttribute(premix_kernel,
                         cudaFuncAttributeMaxDynamicSharedMemorySize, 98304);
    cudaFuncSetAttribute(maingemm_kernel,
                         cudaFuncAttributeMaxDynamicSharedMemorySize, 64 * 200 * 2 * 2);

    consts_kernel<<<NH / 4, 128>>>(log_dt, lAr, Aim, Cre, Cim, Dv, cond, fW, fb);
    premix_kernel<<<dim3(NL / 256, NB), 256, 98304>>>(x, W, b_lin);
    egemm_kernel<<<NB * NH, 512>>>();
    chunk_scan_kernel<<<(NB * NH) / 4, 128>>>();
    maingemm_kernel<<<NB * NH, 256, 64 * 200 * 2 * 2>>>(x, rw, out);
}